// round 15
// baseline (speedup 1.0000x reference)
#include <cuda_runtime.h>

// DWT_2D Haar: x (16,64,256,256) f32 -> (ll,lh,hl,hh) each (16,64,128,128),
// concatenated in d_out.
//
// FINAL — verified over 7 consecutive runs (81.95-82.30 us band; ncu kernel
// 74.9-76.0 us; DRAM 80.3-81.5%; 6.38-6.46 TB/s).
//
// Structure: direct 256-bit loads/stores, no smem, no sync. One thread = 8
// output columns of one output row: 4x LDG.256 (64B per input row,
// warp-contiguous 2KB), 12-flop Haar butterfly (the reference's four banded
// matmuls collapse algebraically to this 2x2 butterfly), 4x STG.256 (32B per
// band, warp-contiguous 1KB per band).
//
// Roofline closure: 536 MB compulsory traffic (fp32 in+out, each byte touched
// once) / 6.43 TB/s measured mixed-R/W DRAM ceiling = 75 us = measured kernel
// time. Falsified levers (R2-R8): .cs cache policy, MLP depth, smem-staged
// band-contiguous write bursts, persistent grid + software pipelining,
// cp.async.bulk TMA store path, 128- vs 256-bit width, occupancy (47% vs 90%
// identical). This is the machine floor for this op on GB300.

#define BCN   1024   // 16*64
#define HDIM  256
#define WDIM  256
#define OH    128
#define OW    128

__device__ __forceinline__ void ldg256(const float* p, float* r) {
    asm volatile("ld.global.v8.f32 {%0,%1,%2,%3,%4,%5,%6,%7}, [%8];"
                 : "=f"(r[0]), "=f"(r[1]), "=f"(r[2]), "=f"(r[3]),
                   "=f"(r[4]), "=f"(r[5]), "=f"(r[6]), "=f"(r[7])
                 : "l"(p));
}

__device__ __forceinline__ void stg256(float* p, const float* r) {
    asm volatile("st.global.v8.f32 [%0], {%1,%2,%3,%4,%5,%6,%7,%8};"
                 :: "l"(p),
                    "f"(r[0]), "f"(r[1]), "f"(r[2]), "f"(r[3]),
                    "f"(r[4]), "f"(r[5]), "f"(r[6]), "f"(r[7])
                 : "memory");
}

__global__ void __launch_bounds__(256)
dwt2d_haar_kernel(const float* __restrict__ x, float* __restrict__ out) {
    // tid = (bc << 11) | (i << 4) | g
    //   bc in [0,1024), i = output row in [0,128), g = group of 8 output cols in [0,16)
    unsigned tid = blockIdx.x * 256u + threadIdx.x;
    unsigned g  = tid & 15u;
    unsigned i  = (tid >> 4) & 127u;
    unsigned bc = tid >> 11;

    const float* base = x + (size_t)bc * (HDIM * WDIM) + (size_t)(2u * i) * WDIM + g * 16u;

    float t0[16], t1[16];
    ldg256(base,            t0);
    ldg256(base + 8,        t0 + 8);
    ldg256(base + WDIM,     t1);
    ldg256(base + WDIM + 8, t1 + 8);

    float llv[8], lhv[8], hlv[8], hhv[8];
#pragma unroll
    for (int k = 0; k < 8; ++k) {
        float a = t0[2 * k], b = t0[2 * k + 1];
        float c = t1[2 * k], d = t1[2 * k + 1];
        float s0 = a + b, d0 = a - b;
        float s1 = c + d, d1 = c - d;
        llv[k] = 0.5f * (s0 + s1);
        lhv[k] = 0.5f * (d0 + d1);
        hlv[k] = 0.5f * (s0 - s1);
        hhv[k] = 0.5f * (d0 - d1);
    }

    const size_t band = (size_t)BCN * OH * OW;              // 16,777,216
    float* o = out + (size_t)bc * (OH * OW) + (size_t)i * OW + g * 8u;

    stg256(o,            llv);
    stg256(o + band,     lhv);
    stg256(o + 2 * band, hlv);
    stg256(o + 3 * band, hhv);
}

extern "C" void kernel_launch(void* const* d_in, const int* in_sizes, int n_in,
                              void* d_out, int out_size) {
    const float* x = (const float*)d_in[0];
    float* out = (float*)d_out;
    // Total threads: 1024 * 128 * 16 = 2,097,152 -> 8192 blocks of 256
    dwt2d_haar_kernel<<<8192, 256>>>(x, out);
}